// round 10
// baseline (speedup 1.0000x reference)
#include <cuda_runtime.h>

// Shapes (fixed per reference): B=1024, C=200, L=3, DIM=512, SEQ=C+1=201
#define B_    1024
#define C_    200
#define DIM_  512
#define SEQ_  201
#define BT    32       // batch rows per block (4x W reuse vs R2; x lives in smem)

// out[b,0,d]   = cls[d] + pe[0,d]
// out[b,c+1,d] = x[b,clamp(c-1)]*W[c,0,d] + x[b,c]*W[c,1,d] + x[b,clamp(c+1)]*W[c,2,d] + pe[c+1,d]

__device__ __forceinline__ void stcs4(float4* p, float4 v) {
    // streaming store: evict-first in L2 — protects L2-resident inputs in the
    // warm graph-replay regime (proven load-bearing R1->R2)
    asm volatile("st.global.cs.v4.f32 [%0], {%1, %2, %3, %4};"
                 :: "l"(p), "f"(v.x), "f"(v.y), "f"(v.z), "f"(v.w) : "memory");
}

__global__ __launch_bounds__(128, 10)
void GSE_band_proj_kernel(const float* __restrict__ x,
                          const float* __restrict__ W,
                          const float* __restrict__ cls,
                          const float* __restrict__ pe,
                          float* __restrict__ out) {
    __shared__ float xs[3][BT];              // 3 x-columns for 32 batch rows (384 B)

    const int d4     = threadIdx.x;          // 0..127 (float4 index into DIM=512)
    const int s      = blockIdx.x;           // 0..200 (sequence position)
    const int b_base = blockIdx.y * BT;

    if (s == 0) {
        // cls row: batch-invariant value, pure store stream
        const float4 cv = reinterpret_cast<const float4*>(cls)[d4];
        const float4 pv = reinterpret_cast<const float4*>(pe)[d4];
        float4 r;
        r.x = cv.x + pv.x;  r.y = cv.y + pv.y;
        r.z = cv.z + pv.z;  r.w = cv.w + pv.w;
        #pragma unroll
        for (int i = 0; i < BT; i++) {
            const size_t b = (size_t)(b_base + i);
            stcs4(reinterpret_cast<float4*>(out + (b * SEQ_) * DIM_) + d4, r);
        }
        return;
    }

    const int c = s - 1;                     // 0..199

    // Cooperative x-window fill: col j in {0,1,2} = x[:, clamp(c-1+j)], 96 threads
    if (threadIdx.x < 3 * BT) {
        const int j = threadIdx.x / BT;      // 0..2
        const int i = threadIdx.x % BT;      // 0..31
        int col = c - 1 + j;
        col = (col < 0) ? 0 : (col > C_ - 1 ? C_ - 1 : col);
        xs[j][i] = __ldg(x + (size_t)(b_base + i) * C_ + col);
    }

    // Per-(c,d4) constants, reused across BT=32 batch rows (L2-resident broadcast).
    const float4 w0 = reinterpret_cast<const float4*>(W + ((size_t)c * 3 + 0) * DIM_)[d4];
    const float4 w1 = reinterpret_cast<const float4*>(W + ((size_t)c * 3 + 1) * DIM_)[d4];
    const float4 w2 = reinterpret_cast<const float4*>(W + ((size_t)c * 3 + 2) * DIM_)[d4];
    const float4 pv = reinterpret_cast<const float4*>(pe + (size_t)(c + 1) * DIM_)[d4];

    __syncthreads();

    // 32 fully independent FMA+STG chains per thread: deep fire-and-forget
    // store MLP (all 32 STG.128 in flight, M_max ~55 per warp)
    #pragma unroll
    for (int i = 0; i < BT; i++) {
        const float a = xs[0][i];            // broadcast LDS (warp-uniform)
        const float m = xs[1][i];
        const float z = xs[2][i];
        float4 r;
        r.x = fmaf(a, w0.x, fmaf(m, w1.x, fmaf(z, w2.x, pv.x)));
        r.y = fmaf(a, w0.y, fmaf(m, w1.y, fmaf(z, w2.y, pv.y)));
        r.z = fmaf(a, w0.z, fmaf(m, w1.z, fmaf(z, w2.z, pv.z)));
        r.w = fmaf(a, w0.w, fmaf(m, w1.w, fmaf(z, w2.w, pv.w)));
        const size_t b = (size_t)(b_base + i);
        stcs4(reinterpret_cast<float4*>(out + (b * SEQ_ + s) * DIM_) + d4, r);
    }
}

extern "C" void kernel_launch(void* const* d_in, const int* in_sizes, int n_in,
                              void* d_out, int out_size) {
    const float* x   = (const float*)d_in[0];
    const float* W   = (const float*)d_in[1];
    const float* cls = (const float*)d_in[2];
    const float* pe  = (const float*)d_in[3];
    float* out = (float*)d_out;

    dim3 grid(SEQ_, B_ / BT, 1);    // 201 x 32 blocks = 6432 CTAs
    dim3 block(DIM_ / 4, 1, 1);     // 128 threads, one float4 each
    GSE_band_proj_kernel<<<grid, block>>>(x, W, cls, pe, out);
}

// round 11
// speedup vs baseline: 1.1387x; 1.1387x over previous
#include <cuda_runtime.h>

// Shapes (fixed per reference): B=1024, C=200, L=3, DIM=512, SEQ=C+1=201
#define B_   1024
#define C_   200
#define DIM_ 512
#define SEQ_ 201
#define BT   8        // batch rows per block

// out[b,0,d]   = cls[d] + pe[0,d]
// out[b,c+1,d] = x[b,clamp(c-1)]*W[c,0,d] + x[b,c]*W[c,1,d] + x[b,clamp(c+1)]*W[c,2,d] + pe[c+1,d]

__device__ __forceinline__ void stcs4(float4* p, float4 v) {
    // streaming store: evict-first in L2 — protects L2-resident inputs in the
    // warm graph-replay regime (proven load-bearing R1->R2)
    asm volatile("st.global.cs.v4.f32 [%0], {%1, %2, %3, %4};"
                 :: "l"(p), "f"(v.x), "f"(v.y), "f"(v.z), "f"(v.w) : "memory");
}

__global__ __launch_bounds__(128, 8)
void GSE_band_proj_kernel(const float* __restrict__ x,
                          const float* __restrict__ W,
                          const float* __restrict__ cls,
                          const float* __restrict__ pe,
                          float* __restrict__ out) {
    // Grid-order swap vs R2: consecutive block IDs share the same s
    // (concurrent CTAs reuse the same W/pe L2 lines), while their stores
    // spread across b (402 KB apart -> uniform L2-slice/HBM-channel coverage).
    const int s  = blockIdx.y;        // 0..200 (sequence position)
    const int d4 = threadIdx.x;       // 0..127 (float4 index into DIM=512)
    const int b_base = blockIdx.x * BT;

    if (s == 0) {
        // cls row: batch-invariant value, pure store stream
        const float4 cv = reinterpret_cast<const float4*>(cls)[d4];
        const float4 pv = reinterpret_cast<const float4*>(pe)[d4];
        float4 r;
        r.x = cv.x + pv.x;
        r.y = cv.y + pv.y;
        r.z = cv.z + pv.z;
        r.w = cv.w + pv.w;
        #pragma unroll
        for (int i = 0; i < BT; i++) {
            const size_t b = (size_t)(b_base + i);
            stcs4(reinterpret_cast<float4*>(out + (b * SEQ_) * DIM_) + d4, r);
        }
        return;
    }

    const int c   = s - 1;                       // 0..199
    const int cm1 = (c > 0)      ? c - 1 : 0;    // edge-replicate pad
    const int cp1 = (c < C_ - 1) ? c + 1 : C_ - 1;

    // Prefetch ALL x values for the 8 batch rows first — fully independent
    // LDGs so the scoreboard overlaps them; the store loop never waits on a load.
    float xa[BT], xm[BT], xz[BT];
    #pragma unroll
    for (int i = 0; i < BT; i++) {
        const size_t row = (size_t)(b_base + i) * C_;
        xa[i] = __ldg(x + row + cm1);
        xm[i] = __ldg(x + row + c);
        xz[i] = __ldg(x + row + cp1);
    }

    // Per-(c,d4) constants, loaded once, reused across BT batch rows.
    const float4 w0 = reinterpret_cast<const float4*>(W + ((size_t)c * 3 + 0) * DIM_)[d4];
    const float4 w1 = reinterpret_cast<const float4*>(W + ((size_t)c * 3 + 1) * DIM_)[d4];
    const float4 w2 = reinterpret_cast<const float4*>(W + ((size_t)c * 3 + 2) * DIM_)[d4];
    const float4 pv = reinterpret_cast<const float4*>(pe + (size_t)(c + 1) * DIM_)[d4];

    #pragma unroll
    for (int i = 0; i < BT; i++) {
        const size_t b = (size_t)(b_base + i);
        float4 r;
        r.x = fmaf(xa[i], w0.x, fmaf(xm[i], w1.x, fmaf(xz[i], w2.x, pv.x)));
        r.y = fmaf(xa[i], w0.y, fmaf(xm[i], w1.y, fmaf(xz[i], w2.y, pv.y)));
        r.z = fmaf(xa[i], w0.z, fmaf(xm[i], w1.z, fmaf(xz[i], w2.z, pv.z)));
        r.w = fmaf(xa[i], w0.w, fmaf(xm[i], w1.w, fmaf(xz[i], w2.w, pv.w)));
        stcs4(reinterpret_cast<float4*>(out + (b * SEQ_ + s) * DIM_) + d4, r);
    }
}

extern "C" void kernel_launch(void* const* d_in, const int* in_sizes, int n_in,
                              void* d_out, int out_size) {
    const float* x   = (const float*)d_in[0];
    const float* W   = (const float*)d_in[1];
    const float* cls = (const float*)d_in[2];
    const float* pe  = (const float*)d_in[3];
    float* out = (float*)d_out;

    dim3 grid(B_ / BT, SEQ_, 1);   // 128 x 201 blocks (b-tiles fastest)
    dim3 block(DIM_ / 4, 1, 1);    // 128 threads, one float4 each
    GSE_band_proj_kernel<<<grid, block>>>(x, W, cls, pe, out);
}

// round 12
// speedup vs baseline: 1.1696x; 1.0271x over previous
#include <cuda_runtime.h>

// Shapes (fixed per reference): B=1024, C=200, L=3, DIM=512, SEQ=C+1=201
#define B_   1024
#define C_   200
#define DIM_ 512
#define SEQ_ 201
#define BT   8        // batch rows per block
#define SP   2        // seq positions per block (two independent 128-thread halves)
#define GRX  ((SEQ_ + SP - 1) / SP)   // 101 (s=201 guarded out)

// out[b,0,d]   = cls[d] + pe[0,d]
// out[b,c+1,d] = x[b,clamp(c-1)]*W[c,0,d] + x[b,c]*W[c,1,d] + x[b,clamp(c+1)]*W[c,2,d] + pe[c+1,d]

__device__ __forceinline__ void stcs4(float4* p, float4 v) {
    // streaming store: evict-first in L2 — protects L2-resident inputs in the
    // warm graph-replay regime (proven load-bearing R1->R2)
    asm volatile("st.global.cs.v4.f32 [%0], {%1, %2, %3, %4};"
                 :: "l"(p), "f"(v.x), "f"(v.y), "f"(v.z), "f"(v.w) : "memory");
}

__global__ __launch_bounds__(256, 4)
void GSE_band_proj_kernel(const float* __restrict__ x,
                          const float* __restrict__ W,
                          const float* __restrict__ cls,
                          const float* __restrict__ pe,
                          float* __restrict__ out) {
    // Two fully independent 128-thread halves per CTA; no smem, no barrier.
    // Each half's instruction stream is identical to the R2 winner.
    const int half = threadIdx.x >> 7;          // 0 or 1
    const int d4   = threadIdx.x & 127;         // 0..127 (float4 index into DIM)
    const int s    = blockIdx.x * SP + half;    // 0..201 (201 guarded)
    const int b_base = blockIdx.y * BT;

    if (s >= SEQ_) return;

    if (s == 0) {
        // cls row: batch-invariant value, pure store stream
        const float4 cv = reinterpret_cast<const float4*>(cls)[d4];
        const float4 pv = reinterpret_cast<const float4*>(pe)[d4];
        float4 r;
        r.x = cv.x + pv.x;
        r.y = cv.y + pv.y;
        r.z = cv.z + pv.z;
        r.w = cv.w + pv.w;
        #pragma unroll
        for (int i = 0; i < BT; i++) {
            const size_t b = (size_t)(b_base + i);
            stcs4(reinterpret_cast<float4*>(out + (b * SEQ_) * DIM_) + d4, r);
        }
        return;
    }

    const int c   = s - 1;                       // 0..199
    const int cm1 = (c > 0)      ? c - 1 : 0;    // edge-replicate pad
    const int cp1 = (c < C_ - 1) ? c + 1 : C_ - 1;

    // Prefetch ALL x values for the 8 batch rows first — fully independent
    // LDGs so the scoreboard overlaps them; the store loop never waits on a load.
    float xa[BT], xm[BT], xz[BT];
    #pragma unroll
    for (int i = 0; i < BT; i++) {
        const size_t row = (size_t)(b_base + i) * C_;
        xa[i] = __ldg(x + row + cm1);
        xm[i] = __ldg(x + row + c);
        xz[i] = __ldg(x + row + cp1);
    }

    // Per-(c,d4) constants, loaded once, reused across BT batch rows.
    const float4 w0 = reinterpret_cast<const float4*>(W + ((size_t)c * 3 + 0) * DIM_)[d4];
    const float4 w1 = reinterpret_cast<const float4*>(W + ((size_t)c * 3 + 1) * DIM_)[d4];
    const float4 w2 = reinterpret_cast<const float4*>(W + ((size_t)c * 3 + 2) * DIM_)[d4];
    const float4 pv = reinterpret_cast<const float4*>(pe + (size_t)(c + 1) * DIM_)[d4];

    #pragma unroll
    for (int i = 0; i < BT; i++) {
        const size_t b = (size_t)(b_base + i);
        float4 r;
        r.x = fmaf(xa[i], w0.x, fmaf(xm[i], w1.x, fmaf(xz[i], w2.x, pv.x)));
        r.y = fmaf(xa[i], w0.y, fmaf(xm[i], w1.y, fmaf(xz[i], w2.y, pv.y)));
        r.z = fmaf(xa[i], w0.z, fmaf(xm[i], w1.z, fmaf(xz[i], w2.z, pv.z)));
        r.w = fmaf(xa[i], w0.w, fmaf(xm[i], w1.w, fmaf(xz[i], w2.w, pv.w)));
        stcs4(reinterpret_cast<float4*>(out + (b * SEQ_ + s) * DIM_) + d4, r);
    }
}

extern "C" void kernel_launch(void* const* d_in, const int* in_sizes, int n_in,
                              void* d_out, int out_size) {
    const float* x   = (const float*)d_in[0];
    const float* W   = (const float*)d_in[1];
    const float* cls = (const float*)d_in[2];
    const float* pe  = (const float*)d_in[3];
    float* out = (float*)d_out;

    dim3 grid(GRX, B_ / BT, 1);    // 101 x 128 blocks = 12928 CTAs
    dim3 block(256, 1, 1);         // two independent 128-thread halves
    GSE_band_proj_kernel<<<grid, block>>>(x, W, cls, pe, out);
}

// round 13
// speedup vs baseline: 1.1708x; 1.0011x over previous
#include <cuda_runtime.h>
#include <cstdint>

// Shapes (fixed per reference): B=1024, C=200, L=3, DIM=512, SEQ=C+1=201
#define B_   1024
#define C_   200
#define DIM_ 512
#define SEQ_ 201
#define BT   8        // batch rows per block
#define SP   2        // seq positions per block (two independent 128-thread halves)
#define GRX  ((SEQ_ + SP - 1) / SP)   // 101 (s=201 guarded out)

// out[b,0,d]   = cls[d] + pe[0,d]
// out[b,c+1,d] = x[b,clamp(c-1)]*W[c,0,d] + x[b,c]*W[c,1,d] + x[b,clamp(c+1)]*W[c,2,d] + pe[c+1,d]

__device__ __forceinline__ void stcs4(float4* p, float4 v) {
    // streaming store: evict-first in L2 — protects L2-resident inputs in the
    // warm graph-replay regime (proven load-bearing R1->R2)
    asm volatile("st.global.cs.v4.f32 [%0], {%1, %2, %3, %4};"
                 :: "l"(p), "f"(v.x), "f"(v.y), "f"(v.z), "f"(v.w) : "memory");
}

__global__ __launch_bounds__(256, 5)
void GSE_band_proj_kernel(const float* __restrict__ x,
                          const float* __restrict__ W,
                          const float* __restrict__ cls,
                          const float* __restrict__ pe,
                          float* __restrict__ out) {
    // Two fully independent 128-thread halves per CTA; no smem, no barrier.
    // All addressing in 32-bit (output = 423 MB < 4 GB) to cut register count.
    const int half = threadIdx.x >> 7;          // 0 or 1
    const int d4   = threadIdx.x & 127;         // 0..127 (float4 index into DIM)
    const int s    = blockIdx.x * SP + half;    // 0..201 (201 guarded)
    const int b_base = blockIdx.y * BT;

    if (s >= SEQ_) return;

    float4* const out4 = reinterpret_cast<float4*>(out);
    const uint32_t d4u = (uint32_t)d4;

    if (s == 0) {
        const float4 cv = reinterpret_cast<const float4*>(cls)[d4];
        const float4 pv = reinterpret_cast<const float4*>(pe)[d4];
        float4 r;
        r.x = cv.x + pv.x;
        r.y = cv.y + pv.y;
        r.z = cv.z + pv.z;
        r.w = cv.w + pv.w;
        // float4 offset of out[b_base, 0, 0]
        uint32_t off = (uint32_t)b_base * (SEQ_ * DIM_ / 4) + d4u;
        #pragma unroll
        for (int i = 0; i < BT; i++) {
            stcs4(out4 + off, r);
            off += SEQ_ * DIM_ / 4;
        }
        return;
    }

    const int c   = s - 1;                       // 0..199
    const int cm1 = (c > 0)      ? c - 1 : 0;    // edge-replicate pad
    const int cp1 = (c < C_ - 1) ? c + 1 : C_ - 1;

    // Prefetch ALL x values for the 8 batch rows — fully independent LDGs;
    // the store loop never waits on a load. 32-bit row offsets.
    float xa[BT], xm[BT], xz[BT];
    {
        uint32_t row = (uint32_t)b_base * C_;
        #pragma unroll
        for (int i = 0; i < BT; i++) {
            xa[i] = __ldg(x + row + cm1);
            xm[i] = __ldg(x + row + c);
            xz[i] = __ldg(x + row + cp1);
            row += C_;
        }
    }

    // Per-(c,d4) constants, loaded once, reused across BT batch rows.
    const float4* W4 = reinterpret_cast<const float4*>(W);
    const uint32_t wbase = (uint32_t)c * (3 * DIM_ / 4) + d4u;
    const float4 w0 = W4[wbase];
    const float4 w1 = W4[wbase + DIM_ / 4];
    const float4 w2 = W4[wbase + 2 * (DIM_ / 4)];
    const float4 pv = reinterpret_cast<const float4*>(pe)[(uint32_t)(c + 1) * (DIM_ / 4) + d4u];

    // float4 offset of out[b_base, s, 0] + d4
    uint32_t off = ((uint32_t)b_base * SEQ_ + (uint32_t)s) * (DIM_ / 4) + d4u;
    #pragma unroll
    for (int i = 0; i < BT; i++) {
        float4 r;
        r.x = fmaf(xa[i], w0.x, fmaf(xm[i], w1.x, fmaf(xz[i], w2.x, pv.x)));
        r.y = fmaf(xa[i], w0.y, fmaf(xm[i], w1.y, fmaf(xz[i], w2.y, pv.y)));
        r.z = fmaf(xa[i], w0.z, fmaf(xm[i], w1.z, fmaf(xz[i], w2.z, pv.z)));
        r.w = fmaf(xa[i], w0.w, fmaf(xm[i], w1.w, fmaf(xz[i], w2.w, pv.w)));
        stcs4(out4 + off, r);
        off += SEQ_ * DIM_ / 4;
    }
}

extern "C" void kernel_launch(void* const* d_in, const int* in_sizes, int n_in,
                              void* d_out, int out_size) {
    const float* x   = (const float*)d_in[0];
    const float* W   = (const float*)d_in[1];
    const float* cls = (const float*)d_in[2];
    const float* pe  = (const float*)d_in[3];
    float* out = (float*)d_out;

    dim3 grid(GRX, B_ / BT, 1);    // 101 x 128 blocks = 12928 CTAs
    dim3 block(256, 1, 1);         // two independent 128-thread halves
    GSE_band_proj_kernel<<<grid, block>>>(x, W, cls, pe, out);
}